// round 1
// baseline (speedup 1.0000x reference)
#include <cuda_runtime.h>
#include <cuda_bf16.h>

#define B_   64
#define H_   512
#define W_   512
#define HW_  (H_ * W_)          // 262144
#define BPS  16                 // blocks per sample
#define TPB  256
#define CHUNK (HW_ / BPS)       // 16384 elements per block
#define NSLOT (B_ * BPS)        // 1024 partial slots

// Per-block partial reductions (SoA). Every slot written each launch -> no init needed.
__device__ float g_fp[3 * NSLOT];   // [0]=sum_p  [1]=sum_pt  [2]=sum_bce
__device__ int   g_ip[7 * NSLOT];   // [0]=sum_t [1]=area [2]=inter [3]=minx [4]=miny [5]=maxx [6]=maxy

__device__ __forceinline__ float warp_sum_f(float v) {
    #pragma unroll
    for (int o = 16; o > 0; o >>= 1) v += __shfl_down_sync(0xffffffffu, v, o);
    return v;
}
__device__ __forceinline__ int warp_sum_i(int v) {
    #pragma unroll
    for (int o = 16; o > 0; o >>= 1) v += __shfl_down_sync(0xffffffffu, v, o);
    return v;
}
__device__ __forceinline__ int warp_min_i(int v) {
    #pragma unroll
    for (int o = 16; o > 0; o >>= 1) v = min(v, __shfl_down_sync(0xffffffffu, v, o));
    return v;
}
__device__ __forceinline__ int warp_max_i(int v) {
    #pragma unroll
    for (int o = 16; o > 0; o >>= 1) v = max(v, __shfl_down_sync(0xffffffffu, v, o));
    return v;
}

__global__ __launch_bounds__(TPB) void uh_reduce_kernel(
    const float* __restrict__ logits,   // (B,1,H,W)
    const int*   __restrict__ tgt,      // (B,H,W)
    const float* __restrict__ pbox)     // (B,4) xywh normalized
{
    const int b   = blockIdx.y;
    const int c   = blockIdx.x;
    const int tid = threadIdx.x;

    // Box in pixel coords (matches jnp: truncate toward zero, then clip [0, W]/[0, H])
    const float cx = pbox[b * 4 + 0], cy = pbox[b * 4 + 1];
    const float bw = pbox[b * 4 + 2], bh = pbox[b * 4 + 3];
    const float bx1 = (cx - bw * 0.5f) * (float)W_;
    const float by1 = (cy - bh * 0.5f) * (float)H_;
    const float bx2 = (cx + bw * 0.5f) * (float)W_;
    const float by2 = (cy + bh * 0.5f) * (float)H_;
    const int x1p = min(max((int)bx1, 0), W_);
    const int x2p = min(max((int)bx2, 0), W_);
    const int y1p = min(max((int)by1, 0), H_);
    const int y2p = min(max((int)by2, 0), H_);

    const float4* lg4 = (const float4*)(logits + (size_t)b * HW_ + (size_t)c * CHUNK);
    const int4*   tg4 = (const int4*)  (tgt    + (size_t)b * HW_ + (size_t)c * CHUNK);

    float sp = 0.f, spt = 0.f, sbce = 0.f;
    int st = 0, area = 0, inter = 0;
    int mnx = W_, mny = H_, mxx = -1, mxy = -1;

    const int ebase = c * CHUNK;

    #pragma unroll 4
    for (int k = 0; k < CHUNK / (4 * TPB); ++k) {
        const int i4 = k * TPB + tid;
        const float4 xv = lg4[i4];
        const int4   tv = tg4[i4];
        const int e  = ebase + i4 * 4;
        const int y  = e >> 9;         // W=512
        const int x0 = e & 511;
        const bool yin = (y >= y1p) && (y < y2p);

        float xs[4] = {xv.x, xv.y, xv.z, xv.w};
        int   ts[4] = {tv.x, tv.y, tv.z, tv.w};

        #pragma unroll
        for (int j = 0; j < 4; ++j) {
            const float x = xs[j];
            const float t = (float)ts[j];
            const float a = fabsf(x);
            const float u = __expf(-a);               // e^{-|x|}
            const float px = __fdividef(1.0f, 1.0f + u);
            const float p = (x >= 0.0f) ? px : 1.0f - px;   // sigmoid(x)
            sp   += p;
            spt  += p * t;
            st   += ts[j];
            // bce = max(x,0) - x*t + log1p(e^{-|x|})
            sbce += fmaxf(x, 0.0f) - x * t + __logf(1.0f + u);

            if (x > 0.0f) {                            // seg_bin (probs > 0.5 <=> x > 0)
                ++area;
                const int xx = x0 + j;
                mnx = min(mnx, xx); mxx = max(mxx, xx);
                mny = min(mny, y);  mxy = max(mxy, y);
                if (yin && xx >= x1p && xx < x2p) ++inter;
            }
        }
    }

    // Block reduce (warp shuffle + shared)
    __shared__ float shf[3][TPB / 32];
    __shared__ int   shi[7][TPB / 32];
    const int lane = tid & 31, wid = tid >> 5;

    sp    = warp_sum_f(sp);
    spt   = warp_sum_f(spt);
    sbce  = warp_sum_f(sbce);
    st    = warp_sum_i(st);
    area  = warp_sum_i(area);
    inter = warp_sum_i(inter);
    mnx   = warp_min_i(mnx);
    mny   = warp_min_i(mny);
    mxx   = warp_max_i(mxx);
    mxy   = warp_max_i(mxy);

    if (lane == 0) {
        shf[0][wid] = sp;   shf[1][wid] = spt;  shf[2][wid] = sbce;
        shi[0][wid] = st;   shi[1][wid] = area; shi[2][wid] = inter;
        shi[3][wid] = mnx;  shi[4][wid] = mny;  shi[5][wid] = mxx; shi[6][wid] = mxy;
    }
    __syncthreads();

    if (tid == 0) {
        float rp = shf[0][0], rpt = shf[1][0], rbce = shf[2][0];
        int rt = shi[0][0], ra = shi[1][0], ri = shi[2][0];
        int r3 = shi[3][0], r4 = shi[4][0], r5 = shi[5][0], r6 = shi[6][0];
        #pragma unroll
        for (int w = 1; w < TPB / 32; ++w) {
            rp += shf[0][w]; rpt += shf[1][w]; rbce += shf[2][w];
            rt += shi[0][w]; ra  += shi[1][w]; ri   += shi[2][w];
            r3 = min(r3, shi[3][w]); r4 = min(r4, shi[4][w]);
            r5 = max(r5, shi[5][w]); r6 = max(r6, shi[6][w]);
        }
        const int slot = b * BPS + c;
        g_fp[0 * NSLOT + slot] = rp;
        g_fp[1 * NSLOT + slot] = rpt;
        g_fp[2 * NSLOT + slot] = rbce;
        g_ip[0 * NSLOT + slot] = rt;
        g_ip[1 * NSLOT + slot] = ra;
        g_ip[2 * NSLOT + slot] = ri;
        g_ip[3 * NSLOT + slot] = r3;
        g_ip[4 * NSLOT + slot] = r4;
        g_ip[5 * NSLOT + slot] = r5;
        g_ip[6 * NSLOT + slot] = r6;
    }
}

// ---------- scalar box helpers (finalize) ----------
__device__ __forceinline__ void xywh2xyxy(const float* w, float* x) {
    x[0] = w[0] - w[2] * 0.5f; x[1] = w[1] - w[3] * 0.5f;
    x[2] = w[0] + w[2] * 0.5f; x[3] = w[1] + w[3] * 0.5f;
}
__device__ __forceinline__ void xyxy2xywh(const float* x, float* w) {
    w[0] = (x[0] + x[2]) * 0.5f; w[1] = (x[1] + x[3]) * 0.5f;
    w[2] = x[2] - x[0];          w[3] = x[3] - x[1];
}
__device__ __forceinline__ float giou_xyxy(const float* a, const float* b) {
    const float ix1 = fmaxf(a[0], b[0]), iy1 = fmaxf(a[1], b[1]);
    const float ix2 = fminf(a[2], b[2]), iy2 = fminf(a[3], b[3]);
    const float inter = fmaxf(ix2 - ix1, 0.f) * fmaxf(iy2 - iy1, 0.f);
    const float aa = fmaxf(a[2] - a[0], 0.f) * fmaxf(a[3] - a[1], 0.f);
    const float ab = fmaxf(b[2] - b[0], 0.f) * fmaxf(b[3] - b[1], 0.f);
    const float un = aa + ab - inter;
    const float iou = inter / fmaxf(un, 1e-6f);
    const float cx1 = fminf(a[0], b[0]), cy1 = fminf(a[1], b[1]);
    const float cx2 = fmaxf(a[2], b[2]), cy2 = fmaxf(a[3], b[3]);
    const float cc = fmaxf(cx2 - cx1, 0.f) * fmaxf(cy2 - cy1, 0.f);
    return iou - (cc - un) / fmaxf(cc, 1e-6f);
}
__device__ __forceinline__ float box_loss(const float* pw, const float* tw) {
    const float l1 = fabsf(pw[0] - tw[0]) + fabsf(pw[1] - tw[1]) +
                     fabsf(pw[2] - tw[2]) + fabsf(pw[3] - tw[3]);
    float ax[4], bx[4];
    xywh2xyxy(pw, ax); xywh2xyxy(tw, bx);
    return l1 + (1.0f - giou_xyxy(ax, bx));
}

__global__ void uh_finalize_kernel(const float* __restrict__ pbox,
                                   const float* __restrict__ gbox,
                                   float* __restrict__ out)
{
    const int b = threadIdx.x;   // 64 threads, one per sample
    float sp = 0.f, spt = 0.f, sbce = 0.f;
    int st = 0, area = 0, inter = 0;
    int mnx = W_, mny = H_, mxx = -1, mxy = -1;
    #pragma unroll
    for (int c = 0; c < BPS; ++c) {
        const int slot = b * BPS + c;
        sp   += g_fp[0 * NSLOT + slot];
        spt  += g_fp[1 * NSLOT + slot];
        sbce += g_fp[2 * NSLOT + slot];
        st   += g_ip[0 * NSLOT + slot];
        area += g_ip[1 * NSLOT + slot];
        inter+= g_ip[2 * NSLOT + slot];
        mnx = min(mnx, g_ip[3 * NSLOT + slot]);
        mny = min(mny, g_ip[4 * NSLOT + slot]);
        mxx = max(mxx, g_ip[5 * NSLOT + slot]);
        mxy = max(mxy, g_ip[6 * NSLOT + slot]);
    }

    // dice
    const float dice = 1.0f - (2.0f * spt + 1.0f) / (sp + (float)st + 1.0f);

    // s2b
    const float iou_s2b = (area > 0) ? ((float)inter / fmaxf((float)area, 1.0f)) : 0.0f;
    const float s2b = 1.0f - iou_s2b;

    // b2s
    float pb[4] = {pbox[b*4+0], pbox[b*4+1], pbox[b*4+2], pbox[b*4+3]};
    float box_xyxy[4];
    xywh2xyxy(pb, box_xyxy);
    float outer[4];
    if (area > 0) {
        outer[0] = (float)mnx; outer[1] = (float)mny;
        outer[2] = (float)mxx; outer[3] = (float)mxy;
    } else {
        outer[0] = outer[1] = outer[2] = outer[3] = 0.0f;
    }
    outer[0] /= (float)W_; outer[1] /= (float)H_;
    outer[2] /= (float)W_; outer[3] /= (float)H_;
    float pred_w[4], tgt_w[4];
    xyxy2xywh(outer, pred_w);
    xyxy2xywh(box_xyxy, tgt_w);
    const float b2s = box_loss(pred_w, tgt_w);

    // det
    float g[4] = {gbox[b*4+0], gbox[b*4+1], gbox[b*4+2], gbox[b*4+3]};
    const float gx1 = g[0] * (0.45f * (float)W_);
    const float gy1 = g[1] * (0.45f * (float)H_);
    const float gx2 = gx1 + 1.0f + g[2] * (0.5f * (float)W_);
    const float gy2 = gy1 + 1.0f + g[3] * (0.5f * (float)H_);
    float gxyxy[4] = {gx1, gy1, gx2, gy2};
    float gtw[4];
    xyxy2xywh(gxyxy, gtw);
    gtw[0] /= (float)H_; gtw[1] /= (float)W_;
    gtw[2] /= (float)H_; gtw[3] /= (float)W_;
    const float det = box_loss(pb, gtw);

    __shared__ float s_dice[B_], s_bce[B_], s_s2b[B_], s_b2s[B_], s_det[B_];
    s_dice[b] = dice; s_bce[b] = sbce; s_s2b[b] = s2b; s_b2s[b] = b2s; s_det[b] = det;
    __syncthreads();

    if (b == 0) {
        float td = 0.f, tb = 0.f, ts = 0.f, t2 = 0.f, te = 0.f;
        for (int i = 0; i < B_; ++i) {
            td += s_dice[i]; tb += s_bce[i]; ts += s_s2b[i];
            t2 += s_b2s[i];  te += s_det[i];
        }
        const float inv_b = 1.0f / (float)B_;
        const float loss = td * inv_b
                         + tb / ((float)B_ * (float)HW_)
                         + te * inv_b * 0.025f
                         + ts * inv_b
                         + t2 * inv_b;
        out[0] = loss;
    }
}

extern "C" void kernel_launch(void* const* d_in, const int* in_sizes, int n_in,
                              void* d_out, int out_size) {
    const float* pred_mask = (const float*)d_in[0];   // (64,1,512,512)
    const float* pred_bbox = (const float*)d_in[1];   // (64,4)
    const float* gt_bbox   = (const float*)d_in[2];   // (64,4)
    const int*   tgt_mask  = (const int*)  d_in[3];   // (64,512,512)
    float* out = (float*)d_out;

    dim3 grid(BPS, B_);
    uh_reduce_kernel<<<grid, TPB>>>(pred_mask, tgt_mask, pred_bbox);
    uh_finalize_kernel<<<1, B_>>>(pred_bbox, gt_bbox, out);
}

// round 2
// speedup vs baseline: 1.0069x; 1.0069x over previous
#include <cuda_runtime.h>
#include <cuda_bf16.h>

#define B_   64
#define H_   512
#define W_   512
#define HW_  (H_ * W_)          // 262144
#define BPS  16                 // blocks per sample
#define TPB  256
#define CHUNK (HW_ / BPS)       // 16384 elements per block
#define NSLOT (B_ * BPS)        // 1024 partial slots (== total blocks)

// Per-block partial reductions (SoA). Every slot written each launch -> no init needed.
__device__ float g_fp[3 * NSLOT];   // [0]=sum_p  [1]=sum_pt  [2]=sum_bce
__device__ int   g_ip[7 * NSLOT];   // [0]=sum_t [1]=area [2]=inter [3]=minx [4]=miny [5]=maxx [6]=maxy
__device__ unsigned int g_cnt;      // block completion counter (zero-init, reset by last block)

__device__ __forceinline__ float warp_sum_f(float v) {
    #pragma unroll
    for (int o = 16; o > 0; o >>= 1) v += __shfl_down_sync(0xffffffffu, v, o);
    return v;
}
__device__ __forceinline__ int warp_sum_i(int v) {
    #pragma unroll
    for (int o = 16; o > 0; o >>= 1) v += __shfl_down_sync(0xffffffffu, v, o);
    return v;
}
__device__ __forceinline__ int warp_min_i(int v) {
    #pragma unroll
    for (int o = 16; o > 0; o >>= 1) v = min(v, __shfl_down_sync(0xffffffffu, v, o));
    return v;
}
__device__ __forceinline__ int warp_max_i(int v) {
    #pragma unroll
    for (int o = 16; o > 0; o >>= 1) v = max(v, __shfl_down_sync(0xffffffffu, v, o));
    return v;
}

// ---------- scalar box helpers ----------
__device__ __forceinline__ void xywh2xyxy(const float* w, float* x) {
    x[0] = w[0] - w[2] * 0.5f; x[1] = w[1] - w[3] * 0.5f;
    x[2] = w[0] + w[2] * 0.5f; x[3] = w[1] + w[3] * 0.5f;
}
__device__ __forceinline__ void xyxy2xywh(const float* x, float* w) {
    w[0] = (x[0] + x[2]) * 0.5f; w[1] = (x[1] + x[3]) * 0.5f;
    w[2] = x[2] - x[0];          w[3] = x[3] - x[1];
}
__device__ __forceinline__ float giou_xyxy(const float* a, const float* b) {
    const float ix1 = fmaxf(a[0], b[0]), iy1 = fmaxf(a[1], b[1]);
    const float ix2 = fminf(a[2], b[2]), iy2 = fminf(a[3], b[3]);
    const float inter = fmaxf(ix2 - ix1, 0.f) * fmaxf(iy2 - iy1, 0.f);
    const float aa = fmaxf(a[2] - a[0], 0.f) * fmaxf(a[3] - a[1], 0.f);
    const float ab = fmaxf(b[2] - b[0], 0.f) * fmaxf(b[3] - b[1], 0.f);
    const float un = aa + ab - inter;
    const float iou = inter / fmaxf(un, 1e-6f);
    const float cx1 = fminf(a[0], b[0]), cy1 = fminf(a[1], b[1]);
    const float cx2 = fmaxf(a[2], b[2]), cy2 = fmaxf(a[3], b[3]);
    const float cc = fmaxf(cx2 - cx1, 0.f) * fmaxf(cy2 - cy1, 0.f);
    return iou - (cc - un) / fmaxf(cc, 1e-6f);
}
__device__ __forceinline__ float box_loss(const float* pw, const float* tw) {
    const float l1 = fabsf(pw[0] - tw[0]) + fabsf(pw[1] - tw[1]) +
                     fabsf(pw[2] - tw[2]) + fabsf(pw[3] - tw[3]);
    float ax[4], bx[4];
    xywh2xyxy(pw, ax); xywh2xyxy(tw, bx);
    return l1 + (1.0f - giou_xyxy(ax, bx));
}

__global__ __launch_bounds__(TPB) void uh_fused_kernel(
    const float* __restrict__ logits,   // (B,1,H,W)
    const int*   __restrict__ tgt,      // (B,H,W)
    const float* __restrict__ pbox,     // (B,4) xywh normalized
    const float* __restrict__ gbox,     // (B,4)
    float* __restrict__ out)
{
    const int b   = blockIdx.y;
    const int c   = blockIdx.x;
    const int tid = threadIdx.x;

    // Box in pixel coords (matches jnp: truncate toward zero, then clip [0, W]/[0, H])
    const float cx = pbox[b * 4 + 0], cy = pbox[b * 4 + 1];
    const float bw = pbox[b * 4 + 2], bh = pbox[b * 4 + 3];
    const int x1p = min(max((int)((cx - bw * 0.5f) * (float)W_), 0), W_);
    const int x2p = min(max((int)((cx + bw * 0.5f) * (float)W_), 0), W_);
    const int y1p = min(max((int)((cy - bh * 0.5f) * (float)H_), 0), H_);
    const int y2p = min(max((int)((cy + bh * 0.5f) * (float)H_), 0), H_);

    const float4* lg4 = (const float4*)(logits + (size_t)b * HW_ + (size_t)c * CHUNK);
    const int4*   tg4 = (const int4*)  (tgt    + (size_t)b * HW_ + (size_t)c * CHUNK);

    float sp = 0.f, spt = 0.f, sbce = 0.f;
    int st = 0, area = 0, inter = 0;
    int mnx = W_, mny = H_, mxx = -1, mxy = -1;

    const int ebase = c * CHUNK;

    #pragma unroll 4
    for (int k = 0; k < CHUNK / (4 * TPB); ++k) {
        const int i4 = k * TPB + tid;
        const float4 xv = lg4[i4];
        const int4   tv = tg4[i4];
        const int e  = ebase + i4 * 4;
        const int y  = e >> 9;         // W=512
        const int x0 = e & 511;
        const bool yin = (y >= y1p) && (y < y2p);
        // j-range inside the box for this 4-wide group
        const int jlo = max(x1p - x0, 0);
        const int jhi = min(x2p - x0, 4);

        const float xs[4] = {xv.x, xv.y, xv.z, xv.w};
        const int   ts[4] = {tv.x, tv.y, tv.z, tv.w};

        int grp_pos = 0;   // any positive in this group (for y min/max)

        #pragma unroll
        for (int j = 0; j < 4; ++j) {
            const float x = xs[j];
            const bool  t = (ts[j] != 0);
            const float a = fabsf(x);
            const float u = __expf(-a);                       // e^{-|x|}
            const float inv1pu = __fdividef(1.0f, 1.0f + u);
            const float p = (x >= 0.0f) ? inv1pu : 1.0f - inv1pu;   // sigmoid(x)
            sp   += p;
            spt  += t ? p : 0.0f;
            st   += t;
            // bce = max(x,0) - x*t + log1p(e^{-|x|})
            sbce += fmaxf(x, 0.0f) - (t ? x : 0.0f) + __logf(1.0f + u);

            const bool pos = (x > 0.0f);                       // seg_bin
            area += pos;
            grp_pos |= pos;
            const int xx = x0 + j;
            mnx = min(mnx, pos ? xx : W_);
            mxx = max(mxx, pos ? xx : -1);
            inter += (pos && yin && j >= jlo && j < jhi);
        }
        mny = min(mny, grp_pos ? y : H_);
        mxy = max(mxy, grp_pos ? y : -1);
    }

    // Block reduce (warp shuffle + shared)
    __shared__ float shf[3][TPB / 32];
    __shared__ int   shi[7][TPB / 32];
    const int lane = tid & 31, wid = tid >> 5;

    sp    = warp_sum_f(sp);
    spt   = warp_sum_f(spt);
    sbce  = warp_sum_f(sbce);
    st    = warp_sum_i(st);
    area  = warp_sum_i(area);
    inter = warp_sum_i(inter);
    mnx   = warp_min_i(mnx);
    mny   = warp_min_i(mny);
    mxx   = warp_max_i(mxx);
    mxy   = warp_max_i(mxy);

    if (lane == 0) {
        shf[0][wid] = sp;   shf[1][wid] = spt;  shf[2][wid] = sbce;
        shi[0][wid] = st;   shi[1][wid] = area; shi[2][wid] = inter;
        shi[3][wid] = mnx;  shi[4][wid] = mny;  shi[5][wid] = mxx; shi[6][wid] = mxy;
    }
    __syncthreads();

    __shared__ bool s_is_last;
    if (tid == 0) {
        float rp = shf[0][0], rpt = shf[1][0], rbce = shf[2][0];
        int rt = shi[0][0], ra = shi[1][0], ri = shi[2][0];
        int r3 = shi[3][0], r4 = shi[4][0], r5 = shi[5][0], r6 = shi[6][0];
        #pragma unroll
        for (int w = 1; w < TPB / 32; ++w) {
            rp += shf[0][w]; rpt += shf[1][w]; rbce += shf[2][w];
            rt += shi[0][w]; ra  += shi[1][w]; ri   += shi[2][w];
            r3 = min(r3, shi[3][w]); r4 = min(r4, shi[4][w]);
            r5 = max(r5, shi[5][w]); r6 = max(r6, shi[6][w]);
        }
        const int slot = b * BPS + c;
        g_fp[0 * NSLOT + slot] = rp;
        g_fp[1 * NSLOT + slot] = rpt;
        g_fp[2 * NSLOT + slot] = rbce;
        g_ip[0 * NSLOT + slot] = rt;
        g_ip[1 * NSLOT + slot] = ra;
        g_ip[2 * NSLOT + slot] = ri;
        g_ip[3 * NSLOT + slot] = r3;
        g_ip[4 * NSLOT + slot] = r4;
        g_ip[5 * NSLOT + slot] = r5;
        g_ip[6 * NSLOT + slot] = r6;

        __threadfence();   // make partials visible before signaling done
        const unsigned int prev = atomicAdd(&g_cnt, 1u);
        s_is_last = (prev == (unsigned int)(NSLOT - 1));
    }
    __syncthreads();
    if (!s_is_last) return;

    // ================= FINALIZE (last block only) =================
    __shared__ float s_dice[B_], s_bce[B_], s_s2b[B_], s_b2s[B_], s_det[B_];

    if (tid < B_) {
        const int s = tid;   // sample index
        float fsp = 0.f, fspt = 0.f, fsbce = 0.f;
        int fst = 0, farea = 0, finter = 0;
        int fmnx = W_, fmny = H_, fmxx = -1, fmxy = -1;
        #pragma unroll
        for (int cc = 0; cc < BPS; ++cc) {
            const int slot = s * BPS + cc;
            fsp   += g_fp[0 * NSLOT + slot];
            fspt  += g_fp[1 * NSLOT + slot];
            fsbce += g_fp[2 * NSLOT + slot];
            fst   += g_ip[0 * NSLOT + slot];
            farea += g_ip[1 * NSLOT + slot];
            finter+= g_ip[2 * NSLOT + slot];
            fmnx = min(fmnx, g_ip[3 * NSLOT + slot]);
            fmny = min(fmny, g_ip[4 * NSLOT + slot]);
            fmxx = max(fmxx, g_ip[5 * NSLOT + slot]);
            fmxy = max(fmxy, g_ip[6 * NSLOT + slot]);
        }

        // dice
        const float dice = 1.0f - (2.0f * fspt + 1.0f) / (fsp + (float)fst + 1.0f);

        // s2b
        const float iou_s2b = (farea > 0) ? ((float)finter / fmaxf((float)farea, 1.0f)) : 0.0f;
        const float s2b = 1.0f - iou_s2b;

        // b2s
        float pb[4] = {pbox[s*4+0], pbox[s*4+1], pbox[s*4+2], pbox[s*4+3]};
        float box_xyxy[4];
        xywh2xyxy(pb, box_xyxy);
        float outer[4];
        if (farea > 0) {
            outer[0] = (float)fmnx; outer[1] = (float)fmny;
            outer[2] = (float)fmxx; outer[3] = (float)fmxy;
        } else {
            outer[0] = outer[1] = outer[2] = outer[3] = 0.0f;
        }
        outer[0] /= (float)W_; outer[1] /= (float)H_;
        outer[2] /= (float)W_; outer[3] /= (float)H_;
        float pred_w[4], tgt_w[4];
        xyxy2xywh(outer, pred_w);
        xyxy2xywh(box_xyxy, tgt_w);
        const float b2s = box_loss(pred_w, tgt_w);

        // det
        float g[4] = {gbox[s*4+0], gbox[s*4+1], gbox[s*4+2], gbox[s*4+3]};
        const float gx1 = g[0] * (0.45f * (float)W_);
        const float gy1 = g[1] * (0.45f * (float)H_);
        const float gx2 = gx1 + 1.0f + g[2] * (0.5f * (float)W_);
        const float gy2 = gy1 + 1.0f + g[3] * (0.5f * (float)H_);
        float gxyxy[4] = {gx1, gy1, gx2, gy2};
        float gtw[4];
        xyxy2xywh(gxyxy, gtw);
        gtw[0] /= (float)H_; gtw[1] /= (float)W_;
        gtw[2] /= (float)H_; gtw[3] /= (float)W_;
        const float det = box_loss(pb, gtw);

        s_dice[s] = dice; s_bce[s] = fsbce; s_s2b[s] = s2b; s_b2s[s] = b2s; s_det[s] = det;
    }
    __syncthreads();

    if (tid == 0) {
        float td = 0.f, tb = 0.f, ts2 = 0.f, t2 = 0.f, te = 0.f;
        for (int i = 0; i < B_; ++i) {
            td += s_dice[i]; tb += s_bce[i]; ts2 += s_s2b[i];
            t2 += s_b2s[i];  te += s_det[i];
        }
        const float inv_b = 1.0f / (float)B_;
        out[0] = td * inv_b
               + tb / ((float)B_ * (float)HW_)
               + te * inv_b * 0.025f
               + ts2 * inv_b
               + t2 * inv_b;
        g_cnt = 0;   // reset for next graph replay (deterministic)
    }
}

extern "C" void kernel_launch(void* const* d_in, const int* in_sizes, int n_in,
                              void* d_out, int out_size) {
    const float* pred_mask = (const float*)d_in[0];   // (64,1,512,512)
    const float* pred_bbox = (const float*)d_in[1];   // (64,4)
    const float* gt_bbox   = (const float*)d_in[2];   // (64,4)
    const int*   tgt_mask  = (const int*)  d_in[3];   // (64,512,512)
    float* out = (float*)d_out;

    dim3 grid(BPS, B_);
    uh_fused_kernel<<<grid, TPB>>>(pred_mask, tgt_mask, pred_bbox, gt_bbox, out);
}

// round 3
// speedup vs baseline: 1.1136x; 1.1059x over previous
#include <cuda_runtime.h>
#include <cuda_bf16.h>

#define B_   64
#define H_   512
#define W_   512
#define HW_  (H_ * W_)          // 262144
#define BPS  16                 // tiles per sample (32 rows each)
#define TPB  256
#define NSLOT (B_ * BPS)        // 1024 partial slots (== total blocks)

// Per-block partial reductions (SoA). Every slot written each launch -> no init needed.
__device__ float g_fp[4 * NSLOT];   // [0]=sum_p [1]=sum_pt [2]=sum_bce [3]=sum_t
__device__ int   g_ip[6 * NSLOT];   // [0]=area [1]=inter [2]=minx [3]=miny [4]=maxx [5]=maxy
__device__ unsigned int g_cnt;      // block completion counter (zero-init, reset by last block)

__device__ __forceinline__ float warp_sum_f(float v) {
    #pragma unroll
    for (int o = 16; o > 0; o >>= 1) v += __shfl_down_sync(0xffffffffu, v, o);
    return v;
}
__device__ __forceinline__ int warp_sum_i(int v) {
    #pragma unroll
    for (int o = 16; o > 0; o >>= 1) v += __shfl_down_sync(0xffffffffu, v, o);
    return v;
}
__device__ __forceinline__ int warp_min_i(int v) {
    #pragma unroll
    for (int o = 16; o > 0; o >>= 1) v = min(v, __shfl_down_sync(0xffffffffu, v, o));
    return v;
}
__device__ __forceinline__ int warp_max_i(int v) {
    #pragma unroll
    for (int o = 16; o > 0; o >>= 1) v = max(v, __shfl_down_sync(0xffffffffu, v, o));
    return v;
}

// ---------- scalar box helpers ----------
__device__ __forceinline__ void xywh2xyxy(const float* w, float* x) {
    x[0] = w[0] - w[2] * 0.5f; x[1] = w[1] - w[3] * 0.5f;
    x[2] = w[0] + w[2] * 0.5f; x[3] = w[1] + w[3] * 0.5f;
}
__device__ __forceinline__ void xyxy2xywh(const float* x, float* w) {
    w[0] = (x[0] + x[2]) * 0.5f; w[1] = (x[1] + x[3]) * 0.5f;
    w[2] = x[2] - x[0];          w[3] = x[3] - x[1];
}
__device__ __forceinline__ float giou_xyxy(const float* a, const float* b) {
    const float ix1 = fmaxf(a[0], b[0]), iy1 = fmaxf(a[1], b[1]);
    const float ix2 = fminf(a[2], b[2]), iy2 = fminf(a[3], b[3]);
    const float inter = fmaxf(ix2 - ix1, 0.f) * fmaxf(iy2 - iy1, 0.f);
    const float aa = fmaxf(a[2] - a[0], 0.f) * fmaxf(a[3] - a[1], 0.f);
    const float ab = fmaxf(b[2] - b[0], 0.f) * fmaxf(b[3] - b[1], 0.f);
    const float un = aa + ab - inter;
    const float iou = inter / fmaxf(un, 1e-6f);
    const float cx1 = fminf(a[0], b[0]), cy1 = fminf(a[1], b[1]);
    const float cx2 = fmaxf(a[2], b[2]), cy2 = fmaxf(a[3], b[3]);
    const float cc = fmaxf(cx2 - cx1, 0.f) * fmaxf(cy2 - cy1, 0.f);
    return iou - (cc - un) / fmaxf(cc, 1e-6f);
}
__device__ __forceinline__ float box_loss(const float* pw, const float* tw) {
    const float l1 = fabsf(pw[0] - tw[0]) + fabsf(pw[1] - tw[1]) +
                     fabsf(pw[2] - tw[2]) + fabsf(pw[3] - tw[3]);
    float ax[4], bx[4];
    xywh2xyxy(pw, ax); xywh2xyxy(tw, bx);
    return l1 + (1.0f - giou_xyxy(ax, bx));
}

__global__ __launch_bounds__(TPB, 5) void uh_fused_kernel(
    const float* __restrict__ logits,   // (B,1,H,W)
    const int*   __restrict__ tgt,      // (B,H,W)
    const float* __restrict__ pbox,     // (B,4) xywh normalized
    const float* __restrict__ gbox,     // (B,4)
    float* __restrict__ out)
{
    const int b   = blockIdx.y;
    const int c   = blockIdx.x;
    const int tid = threadIdx.x;

    // Fixed-column mapping: thread owns float4-column xq across its rows.
    const int xq   = tid & 127;          // float4 column index [0,128)
    const int half = tid >> 7;           // 0/1: which row of each row-pair
    const int x0   = xq << 2;            // pixel column base

    // Box in pixel coords (truncate toward zero, clip to [0,W]/[0,H] like jnp)
    const float cx = pbox[b * 4 + 0], cy = pbox[b * 4 + 1];
    const float bw = pbox[b * 4 + 2], bh = pbox[b * 4 + 3];
    const int x1p = min(max((int)((cx - bw * 0.5f) * (float)W_), 0), W_);
    const int x2p = min(max((int)((cx + bw * 0.5f) * (float)W_), 0), W_);
    const int y1p = min(max((int)((cy - bh * 0.5f) * (float)H_), 0), H_);
    const int y2p = min(max((int)((cy + bh * 0.5f) * (float)H_), 0), H_);

    // Per-thread constant: which of my 4 columns are inside [x1p, x2p)
    int xin = 0;
    #pragma unroll
    for (int j = 0; j < 4; ++j)
        if (x0 + j >= x1p && x0 + j < x2p) xin |= 1 << j;

    const float4* lg4 = (const float4*)(logits + (size_t)b * HW_);
    const int4*   tg4 = (const int4*)  (tgt    + (size_t)b * HW_);

    float sp = 0.f, spt = 0.f, sbce = 0.f, stf = 0.f;
    int area = 0, inter = 0, apos = 0, ylo = H_, yhi = -1;

    const int rowbase = c * 32;

    #pragma unroll 4
    for (int k = 0; k < 16; ++k) {
        const int yl = 2 * k + half;          // local row [0,32)
        const int y  = rowbase + yl;          // global row
        const float4 xv = lg4[(size_t)(y << 7) + xq];
        const int4   tv = tg4[(size_t)(y << 7) + xq];
        const bool yin = (y >= y1p) && (y < y2p);

        int pb = 0;
        {   // pixel macro body, unrolled manually over the 4 lanes
            const float xs[4] = {xv.x, xv.y, xv.z, xv.w};
            const int   ti[4] = {tv.x, tv.y, tv.z, tv.w};
            #pragma unroll
            for (int j = 0; j < 4; ++j) {
                const float x = xs[j];
                const bool  t = (ti[j] != 0);
                const float u = __expf(-fabsf(x));            // e^{-|x|}
                const float v = 1.0f + u;
                const float p0 = __fdividef(1.0f, v);
                const float p  = (x >= 0.0f) ? p0 : 1.0f - p0; // sigmoid(x)
                const float tf = t ? 1.0f : 0.0f;
                sp  += p;
                spt  = fmaf(p, tf, spt);
                stf += tf;
                // max(x,0) - x*t == max(t ? -x : x, 0)
                sbce += fmaxf(t ? -x : x, 0.0f) + __logf(v);
                pb |= (x > 0.0f) ? (1 << j) : 0;
            }
        }
        area += __popc(pb);
        apos |= pb;
        if (pb) { yhi = y; ylo = min(ylo, y); }
        if (yin) inter += __popc(pb & xin);
    }

    // Resolve per-thread x extremes from the 4-bit column mask
    const int mnx = apos ? (x0 + (__ffs(apos) - 1)) : W_;
    const int mxx = apos ? (x0 + (31 - __clz(apos))) : -1;

    // Block reduce (warp shuffle + shared)
    __shared__ float shf[4][TPB / 32];
    __shared__ int   shi[6][TPB / 32];
    const int lane = tid & 31, wid = tid >> 5;

    float rsp  = warp_sum_f(sp);
    float rspt = warp_sum_f(spt);
    float rbce = warp_sum_f(sbce);
    float rstf = warp_sum_f(stf);
    int rarea  = warp_sum_i(area);
    int rinter = warp_sum_i(inter);
    int rmnx   = warp_min_i(mnx);
    int rylo   = warp_min_i(ylo);
    int rmxx   = warp_max_i(mxx);
    int ryhi   = warp_max_i(yhi);

    if (lane == 0) {
        shf[0][wid] = rsp;  shf[1][wid] = rspt; shf[2][wid] = rbce; shf[3][wid] = rstf;
        shi[0][wid] = rarea; shi[1][wid] = rinter;
        shi[2][wid] = rmnx;  shi[3][wid] = rylo; shi[4][wid] = rmxx; shi[5][wid] = ryhi;
    }
    __syncthreads();

    __shared__ bool s_is_last;
    if (tid == 0) {
        float a0 = shf[0][0], a1 = shf[1][0], a2 = shf[2][0], a3 = shf[3][0];
        int i0 = shi[0][0], i1 = shi[1][0];
        int i2 = shi[2][0], i3 = shi[3][0], i4 = shi[4][0], i5 = shi[5][0];
        #pragma unroll
        for (int w = 1; w < TPB / 32; ++w) {
            a0 += shf[0][w]; a1 += shf[1][w]; a2 += shf[2][w]; a3 += shf[3][w];
            i0 += shi[0][w]; i1 += shi[1][w];
            i2 = min(i2, shi[2][w]); i3 = min(i3, shi[3][w]);
            i4 = max(i4, shi[4][w]); i5 = max(i5, shi[5][w]);
        }
        const int slot = b * BPS + c;
        g_fp[0 * NSLOT + slot] = a0;
        g_fp[1 * NSLOT + slot] = a1;
        g_fp[2 * NSLOT + slot] = a2;
        g_fp[3 * NSLOT + slot] = a3;
        g_ip[0 * NSLOT + slot] = i0;
        g_ip[1 * NSLOT + slot] = i1;
        g_ip[2 * NSLOT + slot] = i2;
        g_ip[3 * NSLOT + slot] = i3;
        g_ip[4 * NSLOT + slot] = i4;
        g_ip[5 * NSLOT + slot] = i5;

        __threadfence();   // make partials visible before signaling done
        const unsigned int prev = atomicAdd(&g_cnt, 1u);
        s_is_last = (prev == (unsigned int)(NSLOT - 1));
    }
    __syncthreads();
    if (!s_is_last) return;

    // ================= FINALIZE (last block only) =================
    __shared__ float s_dice[B_], s_bce[B_], s_s2b[B_], s_b2s[B_], s_det[B_];

    if (tid < B_) {
        const int s = tid;   // sample index
        float fsp = 0.f, fspt = 0.f, fsbce = 0.f, fst = 0.f;
        int farea = 0, finter = 0;
        int fmnx = W_, fmny = H_, fmxx = -1, fmxy = -1;
        #pragma unroll
        for (int cc = 0; cc < BPS; ++cc) {
            const int slot = s * BPS + cc;
            fsp   += g_fp[0 * NSLOT + slot];
            fspt  += g_fp[1 * NSLOT + slot];
            fsbce += g_fp[2 * NSLOT + slot];
            fst   += g_fp[3 * NSLOT + slot];
            farea += g_ip[0 * NSLOT + slot];
            finter+= g_ip[1 * NSLOT + slot];
            fmnx = min(fmnx, g_ip[2 * NSLOT + slot]);
            fmny = min(fmny, g_ip[3 * NSLOT + slot]);
            fmxx = max(fmxx, g_ip[4 * NSLOT + slot]);
            fmxy = max(fmxy, g_ip[5 * NSLOT + slot]);
        }

        // dice
        const float dice = 1.0f - (2.0f * fspt + 1.0f) / (fsp + fst + 1.0f);

        // s2b
        const float iou_s2b = (farea > 0) ? ((float)finter / fmaxf((float)farea, 1.0f)) : 0.0f;
        const float s2b = 1.0f - iou_s2b;

        // b2s
        float pb[4] = {pbox[s*4+0], pbox[s*4+1], pbox[s*4+2], pbox[s*4+3]};
        float box_xyxy[4];
        xywh2xyxy(pb, box_xyxy);
        float outer[4];
        if (farea > 0) {
            outer[0] = (float)fmnx; outer[1] = (float)fmny;
            outer[2] = (float)fmxx; outer[3] = (float)fmxy;
        } else {
            outer[0] = outer[1] = outer[2] = outer[3] = 0.0f;
        }
        outer[0] /= (float)W_; outer[1] /= (float)H_;
        outer[2] /= (float)W_; outer[3] /= (float)H_;
        float pred_w[4], tgt_w[4];
        xyxy2xywh(outer, pred_w);
        xyxy2xywh(box_xyxy, tgt_w);
        const float b2s = box_loss(pred_w, tgt_w);

        // det
        float g[4] = {gbox[s*4+0], gbox[s*4+1], gbox[s*4+2], gbox[s*4+3]};
        const float gx1 = g[0] * (0.45f * (float)W_);
        const float gy1 = g[1] * (0.45f * (float)H_);
        const float gx2 = gx1 + 1.0f + g[2] * (0.5f * (float)W_);
        const float gy2 = gy1 + 1.0f + g[3] * (0.5f * (float)H_);
        float gxyxy[4] = {gx1, gy1, gx2, gy2};
        float gtw[4];
        xyxy2xywh(gxyxy, gtw);
        gtw[0] /= (float)H_; gtw[1] /= (float)W_;
        gtw[2] /= (float)H_; gtw[3] /= (float)W_;
        const float det = box_loss(pb, gtw);

        s_dice[s] = dice; s_bce[s] = fsbce; s_s2b[s] = s2b; s_b2s[s] = b2s; s_det[s] = det;
    }
    __syncthreads();

    if (tid == 0) {
        float td = 0.f, tb = 0.f, ts2 = 0.f, t2 = 0.f, te = 0.f;
        for (int i = 0; i < B_; ++i) {
            td += s_dice[i]; tb += s_bce[i]; ts2 += s_s2b[i];
            t2 += s_b2s[i];  te += s_det[i];
        }
        const float inv_b = 1.0f / (float)B_;
        out[0] = td * inv_b
               + tb / ((float)B_ * (float)HW_)
               + te * inv_b * 0.025f
               + ts2 * inv_b
               + t2 * inv_b;
        g_cnt = 0;   // reset for next graph replay (deterministic)
    }
}

extern "C" void kernel_launch(void* const* d_in, const int* in_sizes, int n_in,
                              void* d_out, int out_size) {
    const float* pred_mask = (const float*)d_in[0];   // (64,1,512,512)
    const float* pred_bbox = (const float*)d_in[1];   // (64,4)
    const float* gt_bbox   = (const float*)d_in[2];   // (64,4)
    const int*   tgt_mask  = (const int*)  d_in[3];   // (64,512,512)
    float* out = (float*)d_out;

    dim3 grid(BPS, B_);
    uh_fused_kernel<<<grid, TPB>>>(pred_mask, tgt_mask, pred_bbox, gt_bbox, out);
}